// round 1
// baseline (speedup 1.0000x reference)
#include <cuda_runtime.h>

#define KCODES 256
#define DIM 32

// Zero the counts region of the output (it is poisoned to 0xAA by the harness).
__global__ void vq_zero_counts(float* counts) {
    counts[threadIdx.x] = 0.0f;
}

__global__ __launch_bounds__(256) void vq_kernel(
    const float* __restrict__ x,
    const float* __restrict__ cb,
    float* __restrict__ out_rot,
    float* __restrict__ out_idx,
    float* __restrict__ out_counts,
    int N)
{
    __shared__ __align__(16) float cb_s[KCODES * DIM];   // 32 KB
    __shared__ float c2_s[KCODES];
    __shared__ float hist[KCODES];

    const int tid = threadIdx.x;

    // --- Stage codebook into shared memory; compute c2 per code ---
    // c2 replicates reference: square each element (rounded), then sequential sum.
    {
        const float4* src = reinterpret_cast<const float4*>(cb + tid * DIM);
        float4* dst = reinterpret_cast<float4*>(cb_s + tid * DIM);
        float row[DIM];
        #pragma unroll
        for (int j = 0; j < 8; j++) {
            float4 v = src[j];
            dst[j] = v;
            row[4 * j + 0] = v.x; row[4 * j + 1] = v.y;
            row[4 * j + 2] = v.z; row[4 * j + 3] = v.w;
        }
        float s = 0.0f;
        #pragma unroll
        for (int d = 0; d < DIM; d++)
            s = __fadd_rn(s, __fmul_rn(row[d], row[d]));
        c2_s[tid] = s;
        hist[tid] = 0.0f;
    }
    __syncthreads();

    const int t = blockIdx.x * 256 + tid;

    // --- Load token x into registers ---
    float xr[DIM];
    {
        const float4* xp = reinterpret_cast<const float4*>(x + (size_t)t * DIM);
        #pragma unroll
        for (int j = 0; j < 8; j++) {
            float4 v = xp[j];
            xr[4 * j + 0] = v.x; xr[4 * j + 1] = v.y;
            xr[4 * j + 2] = v.z; xr[4 * j + 3] = v.w;
        }
    }

    // x2 = sum(x*x): per-element rounded square, sequential sum (reference order).
    float x2 = 0.0f;
    #pragma unroll
    for (int d = 0; d < DIM; d++)
        x2 = __fadd_rn(x2, __fmul_rn(xr[d], xr[d]));

    // --- Argmin over codes: d2 = fl(fl(x2 - 2*dot) + c2), first-index tie-break ---
    float best = 3.4e38f;
    int bi = 0;
    #pragma unroll 4
    for (int k = 0; k < KCODES; k++) {
        const float4* crow = reinterpret_cast<const float4*>(cb_s + k * DIM);
        float dot = 0.0f;
        #pragma unroll
        for (int j = 0; j < 8; j++) {
            float4 c = crow[j];  // broadcast LDS.128 (all lanes same address)
            dot = __fmaf_rn(xr[4 * j + 0], c.x, dot);
            dot = __fmaf_rn(xr[4 * j + 1], c.y, dot);
            dot = __fmaf_rn(xr[4 * j + 2], c.z, dot);
            dot = __fmaf_rn(xr[4 * j + 3], c.w, dot);
        }
        float t1 = __fadd_rn(x2, __fmul_rn(-2.0f, dot));
        float d2 = __fadd_rn(t1, c2_s[k]);
        if (d2 < best) { best = d2; bi = k; }  // strict <, ascending k == argmin first-index
    }

    // --- Histogram (block-local then global) ---
    atomicAdd(&hist[bi], 1.0f);

    // --- Rotation-trick output ---
    // u = x/max(||x||,eps), qh = q/max(||q||,eps), w = l2norm(u+qh)
    // rotated = x - 2(x.w)w + 2(x.u)qh  ==  x*s1 + q*s2 (algebraic contraction; loose tol)
    float q[DIM];
    #pragma unroll
    for (int d = 0; d < DIM; d++) q[d] = cb_s[bi * DIM + d];

    float q2 = 0.0f, dotq = 0.0f;
    #pragma unroll
    for (int d = 0; d < DIM; d++) {
        q2   = __fmaf_rn(q[d], q[d], q2);
        dotq = __fmaf_rn(xr[d], q[d], dotq);
    }
    const float eps = 1e-6f;
    float inx = 1.0f / fmaxf(sqrtf(x2), eps);
    float inq = 1.0f / fmaxf(sqrtf(q2), eps);
    float u2  = x2 * inx * inx;                 // ~1
    float qh2 = q2 * inq * inq;                 // ~1
    float uq  = dotq * inx * inq;               // u . qh
    float w2  = u2 + qh2 + 2.0f * uq;
    float iw  = 1.0f / fmaxf(sqrtf(w2), eps);
    float ew_un = x2 * inx + dotq * inq;        // x . (u + qh)
    float ew  = ew_un * iw;                     // x . w
    float eu  = x2 * inx;                       // x . u
    float a   = -2.0f * ew * iw;
    float s1  = 1.0f + a * inx;                 // coefficient of x
    float s2  = (a + 2.0f * eu) * inq;          // coefficient of q

    float4* rp = reinterpret_cast<float4*>(out_rot + (size_t)t * DIM);
    #pragma unroll
    for (int j = 0; j < 8; j++) {
        float4 v;
        v.x = xr[4 * j + 0] * s1 + q[4 * j + 0] * s2;
        v.y = xr[4 * j + 1] * s1 + q[4 * j + 1] * s2;
        v.z = xr[4 * j + 2] * s1 + q[4 * j + 2] * s2;
        v.w = xr[4 * j + 3] * s1 + q[4 * j + 3] * s2;
        rp[j] = v;
    }
    out_idx[t] = (float)bi;

    __syncthreads();
    atomicAdd(&out_counts[tid], hist[tid]);
}

extern "C" void kernel_launch(void* const* d_in, const int* in_sizes, int n_in,
                              void* d_out, int out_size) {
    const float* x  = (const float*)d_in[0];
    const float* cb = (const float*)d_in[1];
    float* out = (float*)d_out;

    const int N = in_sizes[0] / DIM;            // 524288
    float* rot    = out;
    float* idx    = out + (size_t)N * DIM;
    float* counts = idx + N;

    vq_zero_counts<<<1, KCODES>>>(counts);
    vq_kernel<<<N / 256, 256>>>(x, cb, rot, idx, counts, N);
}